// round 1
// baseline (speedup 1.0000x reference)
#include <cuda_runtime.h>

// Constants derived from weights (computed once per launch by prep_kernel):
// [0..3]   : 0.5 * w[0][q][0]                (layer-0 RY half-angles, fused with embedding)
// [4..7]   : cos(0.5 * w[1][q][0])           (layer-1 RY)
// [8..11]  : sin(0.5 * w[1][q][0])
// [12..43] : (cos PHI_i, sin PHI_i) i=0..15  (folded layer-0 RZ phases, global phase dropped)
__device__ __align__(16) float g_const[48];

__global__ void prep_kernel(const float* __restrict__ w) {
    if (threadIdx.x == 0 && blockIdx.x == 0) {
        for (int q = 0; q < 4; ++q)
            g_const[q] = 0.5f * w[q * 2 + 0];
        for (int q = 0; q < 4; ++q) {
            float h = 0.5f * w[8 + q * 2 + 0];
            g_const[4 + q] = cosf(h);
            g_const[8 + q] = sinf(h);
        }
        for (int i = 0; i < 16; ++i) {
            float ph = 0.f;
            for (int q = 0; q < 4; ++q)
                if ((i >> (3 - q)) & 1) ph += w[q * 2 + 1];
            g_const[12 + 2 * i]     = cosf(ph);
            g_const[12 + 2 * i + 1] = sinf(ph);
        }
        g_const[44] = g_const[45] = g_const[46] = g_const[47] = 0.f;
    }
}

// CNOT ring permutation: gates (0,1),(1,2),(2,3),(3,0) in time order.
// Index i = b0*8 + b1*4 + b2*2 + b3 (qubit q <-> bit (3-q)).
// state_after[i] = state_before[PERM(i)].
__host__ __device__ constexpr int cnot_m(int i, int cbit, int tbit) {
    return ((i >> cbit) & 1) ? (i ^ (1 << tbit)) : i;
}
__host__ __device__ constexpr int PERM(int i) {
    int j = cnot_m(i, 0, 3);  // last gate:  CNOT(3,0)
    j = cnot_m(j, 1, 0);      //             CNOT(2,3)
    j = cnot_m(j, 2, 1);      //             CNOT(1,2)
    j = cnot_m(j, 3, 2);      // first gate: CNOT(0,1)
    return j;
}

__device__ __forceinline__ float fast_tanh(float v) {
    // tanh(v) = 1 - 2/(1+e^{2v}); MUFU ex2 + rcp, ~1e-6 abs error (safe vs 1e-3 gate)
    float e = __expf(2.0f * v);
    return 1.0f - __fdividef(2.0f, e + 1.0f);
}

__global__ void __launch_bounds__(256) qsim_kernel(const float* __restrict__ x,
                                                   float* __restrict__ out, int B) {
    int b = blockIdx.x * blockDim.x + threadIdx.x;
    if (b >= B) return;

    // x row has 8 floats; only first 4 used
    float4 xv = reinterpret_cast<const float4*>(x)[2 * b];
    float xin[4] = {xv.x, xv.y, xv.z, xv.w};

    // fused embedding + layer-0 RY half-angles; per-qubit (cos, sin)
    float cq[4], sq[4];
    const float HPI = 1.57079632679489662f;  // pi/2 (tanh * pi, then half-angle)
#pragma unroll
    for (int q = 0; q < 4; ++q) {
        float t   = fast_tanh(xin[q]);
        float phi = fmaf(t, HPI, g_const[q]);
        __sincosf(phi, &sq[q], &cq[q]);
    }

    // real product state amp0[i] = prod_q v_q[b_q]
    float a01[4] = {cq[0] * cq[1], cq[0] * sq[1], sq[0] * cq[1], sq[0] * sq[1]};
    float a2[8];
#pragma unroll
    for (int j = 0; j < 4; ++j) { a2[2 * j] = a01[j] * cq[2]; a2[2 * j + 1] = a01[j] * sq[2]; }
    float r[16];
#pragma unroll
    for (int j = 0; j < 8; ++j) { r[2 * j] = a2[j] * cq[3]; r[2 * j + 1] = a2[j] * sq[3]; }

    // layer-0 RZ phases + layer-0 CNOT ring, both folded at compile time:
    // re/im[i] = r[PERM(i)] * e^{i * PHI[PERM(i)]}
    float re[16], im[16];
#pragma unroll
    for (int i = 0; i < 16; ++i) {
        const int p = PERM(i);
        float rp = r[p];
        re[i] = rp * g_const[12 + 2 * p];
        im[i] = rp * g_const[12 + 2 * p + 1];
    }

    // layer-1 RY gates (shared angles)
#pragma unroll
    for (int q = 0; q < 4; ++q) {
        const int m = 8 >> q;
        const float c = g_const[4 + q], s = g_const[8 + q];
        const float ns = -s;
#pragma unroll
        for (int i = 0; i < 16; ++i) {
            if (i & m) continue;
            const int j = i | m;
            float r0 = re[i], r1 = re[j], i0 = im[i], i1 = im[j];
            re[i] = fmaf(c, r0, ns * r1);
            re[j] = fmaf(s, r0, c * r1);
            im[i] = fmaf(c, i0, ns * i1);
            im[j] = fmaf(s, i0, c * i1);
        }
    }
    // layer-1 RZ: diagonal phases before CNOT+measurement -> no effect on probs (dropped)

    // probabilities with layer-1 CNOT ring folded: p_final[i] = |amp[PERM(i)]|^2
    float p[16];
#pragma unroll
    for (int i = 0; i < 16; ++i) {
        const int s_ = PERM(i);
        p[i] = fmaf(re[s_], re[s_], im[s_] * im[s_]);
    }

    // z_q = sum_i (1 - 2*bit_{3-q}(i)) * p[i], via butterfly (shared partial sums)
    float e0[8], d0[8];
#pragma unroll
    for (int k = 0; k < 8; ++k) { e0[k] = p[2 * k] + p[2 * k + 1]; d0[k] = p[2 * k] - p[2 * k + 1]; }
    float z3 = ((d0[0] + d0[1]) + (d0[2] + d0[3])) + ((d0[4] + d0[5]) + (d0[6] + d0[7]));
    float e1[4], d1[4];
#pragma unroll
    for (int k = 0; k < 4; ++k) { e1[k] = e0[2 * k] + e0[2 * k + 1]; d1[k] = e0[2 * k] - e0[2 * k + 1]; }
    float z2 = (d1[0] + d1[1]) + (d1[2] + d1[3]);
    float z1 = (e1[0] - e1[1]) + (e1[2] - e1[3]);
    float z0 = (e1[0] + e1[1]) - (e1[2] + e1[3]);

    float4 o;
    o.x = z0; o.y = z1; o.z = z2; o.w = z3;
    reinterpret_cast<float4*>(out)[b] = o;
}

extern "C" void kernel_launch(void* const* d_in, const int* in_sizes, int n_in,
                              void* d_out, int out_size) {
    const float* x = (const float*)d_in[0];
    const float* w = (const float*)d_in[1];
    float* out = (float*)d_out;
    const int B = in_sizes[0] / 8;

    prep_kernel<<<1, 32>>>(w);
    qsim_kernel<<<(B + 255) / 256, 256>>>(x, out, B);
}

// round 2
// speedup vs baseline: 1.3208x; 1.3208x over previous
#include <cuda_runtime.h>

typedef unsigned long long u64;

// ---- f32x2 packed math (Blackwell FFMA2 via PTX; not emitted by ptxas from C++) ----
__device__ __forceinline__ u64 pk2(float lo, float hi) {
    u64 d; asm("mov.b64 %0, {%1, %2};" : "=l"(d) : "f"(lo), "f"(hi)); return d;
}
__device__ __forceinline__ void upk2(float& lo, float& hi, u64 v) {
    asm("mov.b64 {%0, %1}, %2;" : "=f"(lo), "=f"(hi) : "l"(v));
}
__device__ __forceinline__ u64 mul2(u64 a, u64 b) {
    u64 d; asm("mul.rn.f32x2 %0, %1, %2;" : "=l"(d) : "l"(a), "l"(b)); return d;
}
__device__ __forceinline__ u64 fma2(u64 a, u64 b, u64 c) {
    u64 d; asm("fma.rn.f32x2 %0, %1, %2, %3;" : "=l"(d) : "l"(a), "l"(b), "l"(c)); return d;
}

// CNOT ring permutation: gates (0,1),(1,2),(2,3),(3,0) in time order.
// Index i = b0*8 + b1*4 + b2*2 + b3 (qubit q <-> bit (3-q)).
__host__ __device__ constexpr int cnot_m(int i, int cbit, int tbit) {
    return ((i >> cbit) & 1) ? (i ^ (1 << tbit)) : i;
}
__host__ __device__ constexpr int PERM(int i) {
    int j = cnot_m(i, 0, 3);  // last gate:  CNOT(3,0)
    j = cnot_m(j, 1, 0);      //             CNOT(2,3)
    j = cnot_m(j, 2, 1);      //             CNOT(1,2)
    j = cnot_m(j, 3, 2);      // first gate: CNOT(0,1)
    return j;
}

__global__ void __launch_bounds__(256) qsim_kernel(const float* __restrict__ x,
                                                   const float* __restrict__ w,
                                                   float* __restrict__ out, int B) {
    // Weight-derived constants, computed cooperatively by warp 0 (no prep kernel).
    __shared__ float s_half0[4];   // 0.5 * w[0][q][0]  (layer-0 RY, fused w/ embedding)
    __shared__ float s_c1[4];      // cos(0.5 * w[1][q][0])
    __shared__ float s_s1[4];      // sin(0.5 * w[1][q][0])
    __shared__ u64   s_ph[16];     // packed (cos PHI_i, sin PHI_i): folded layer-0 RZ

    const int tid = threadIdx.x;
    if (tid < 16) {
        float ph = 0.f;
#pragma unroll
        for (int q = 0; q < 4; ++q)
            if ((tid >> (3 - q)) & 1) ph += w[q * 2 + 1];
        float s, c; __sincosf(ph, &s, &c);
        s_ph[tid] = pk2(c, s);
    } else if (tid < 20) {
        int q = tid - 16;
        float s, c; __sincosf(0.5f * w[8 + q * 2], &s, &c);
        s_c1[q] = c; s_s1[q] = s;
    } else if (tid < 24) {
        int q = tid - 20;
        s_half0[q] = 0.5f * w[q * 2];
    }
    __syncthreads();

    const int b = blockIdx.x * 256 + tid;
    if (b >= B) return;

    // x row has 8 floats; only first 4 used
    float4 xv = reinterpret_cast<const float4*>(x)[2 * b];
    float xin[4] = {xv.x, xv.y, xv.z, xv.w};

    // fused embedding + layer-0 RY half-angles
    float cq[4], sq[4];
    const float HPI = 1.57079632679489662f;
#pragma unroll
    for (int q = 0; q < 4; ++q) {
        float e   = __expf(2.0f * xin[q]);
        float t   = 1.0f - __fdividef(2.0f, e + 1.0f);  // tanh, ~1e-6 abs err
        float phi = fmaf(t, HPI, s_half0[q]);
        __sincosf(phi, &sq[q], &cq[q]);
    }

    // real product state r[i] = prod_q v_q[b_q]
    float a01[4] = {cq[0] * cq[1], cq[0] * sq[1], sq[0] * cq[1], sq[0] * sq[1]};
    float a2[8];
#pragma unroll
    for (int j = 0; j < 4; ++j) { a2[2 * j] = a01[j] * cq[2]; a2[2 * j + 1] = a01[j] * sq[2]; }
    float r[16];
#pragma unroll
    for (int j = 0; j < 8; ++j) { r[2 * j] = a2[j] * cq[3]; r[2 * j + 1] = a2[j] * sq[3]; }

    // layer-0 RZ phase + layer-0 CNOT ring folded: amp[i] = r[PERM(i)] * e^{i PHI[PERM(i)]}
    // amp packed as (re, im) f32x2
    u64 amp[16];
#pragma unroll
    for (int i = 0; i < 16; ++i) {
        const int p = PERM(i);
        amp[i] = mul2(pk2(r[p], r[p]), s_ph[p]);
    }

    // layer-1 RY gates (shared angles), packed butterflies
#pragma unroll
    for (int q = 0; q < 4; ++q) {
        const int m = 8 >> q;
        const float c = s_c1[q], s = s_s1[q];
        const u64 c2 = pk2(c, c), s2 = pk2(s, s), ns2 = pk2(-s, -s);
#pragma unroll
        for (int i = 0; i < 16; ++i) {
            if (i & m) continue;
            const int j = i | m;
            u64 ai = amp[i], aj = amp[j];
            amp[i] = fma2(c2, ai, mul2(ns2, aj));
            amp[j] = fma2(s2, ai, mul2(c2, aj));
        }
    }
    // layer-1 RZ: diagonal before CNOTs + measurement -> unobservable (dropped)

    // probabilities with layer-1 CNOT ring folded: p[i] = |amp[PERM(i)]|^2
    float p[16];
#pragma unroll
    for (int i = 0; i < 16; ++i) {
        const int s_ = PERM(i);
        u64 sqv = mul2(amp[s_], amp[s_]);
        float lo, hi; upk2(lo, hi, sqv);
        p[i] = lo + hi;
    }

    // z_q = sum_i (1 - 2*bit_{3-q}(i)) * p[i], via butterfly
    float e0[8], d0[8];
#pragma unroll
    for (int k = 0; k < 8; ++k) { e0[k] = p[2 * k] + p[2 * k + 1]; d0[k] = p[2 * k] - p[2 * k + 1]; }
    float z3 = ((d0[0] + d0[1]) + (d0[2] + d0[3])) + ((d0[4] + d0[5]) + (d0[6] + d0[7]));
    float e1[4], d1[4];
#pragma unroll
    for (int k = 0; k < 4; ++k) { e1[k] = e0[2 * k] + e0[2 * k + 1]; d1[k] = e0[2 * k] - e0[2 * k + 1]; }
    float z2 = (d1[0] + d1[1]) + (d1[2] + d1[3]);
    float z1 = (e1[0] - e1[1]) + (e1[2] - e1[3]);
    float z0 = (e1[0] + e1[1]) - (e1[2] + e1[3]);

    float4 o;
    o.x = z0; o.y = z1; o.z = z2; o.w = z3;
    reinterpret_cast<float4*>(out)[b] = o;
}

extern "C" void kernel_launch(void* const* d_in, const int* in_sizes, int n_in,
                              void* d_out, int out_size) {
    const float* x = (const float*)d_in[0];
    const float* w = (const float*)d_in[1];
    float* out = (float*)d_out;
    const int B = in_sizes[0] / 8;

    qsim_kernel<<<(B + 255) / 256, 256>>>(x, w, out, B);
}